// round 12
// baseline (speedup 1.0000x reference)
#include <cuda_runtime.h>
#include <cstdint>

// Problem constants
#define TT 128
#define SS 512
#define BB 512
#define GRID_F 148           // one CTA per SM, single wave
#define ENG 2                // 128-thread engines per CTA (256 thr)
#define NENG (GRID_F*ENG)    // 296 engines; each handles 2 batches -> 592 slots

__device__ float g_res[BB];  // per-batch (numerator - denominator)

__device__ __forceinline__ float fex2(float x){ float r; asm("ex2.approx.f32 %0,%1;":"=f"(r):"f"(x)); return r; }
__device__ __forceinline__ float flg2(float x){ float r; asm("lg2.approx.f32 %0,%1;":"=f"(r):"f"(x)); return r; }

#define FMA2(d,a,b,c) asm("fma.rn.f32x2 %0,%1,%2,%3;":"=l"(d):"l"(a),"l"(b),"l"(c))
#define ADD2(d,a,b)   asm("add.rn.f32x2 %0,%1,%2;":"=l"(d):"l"(a),"l"(b))
#define UNPK(lo_,hi_,v) asm("mov.b64 {%0,%1},%2;":"=f"(lo_),"=f"(hi_):"l"(v))

#define L2E 1.4426950408889634f
#define LN2 0.6931471805599453f

// ---------------------------------------------------------------------------
// Engine = 128 threads, TWO batches software-pipelined half a step apart.
// Thread t owns full column E[:,t] = exp(trans[:,t]) as 64 f32x2 reg pairs.
// Slot A: barrier; GEMV batch0 step s  || tail batch1 step s-1 (reduce, lg2,
//         masked update with delayed renormalizer K, ex2, publish p1(s)).
// Slot B: barrier; GEMV batch1 step s  || tail batch0 step s.
// The serial tail of one batch hides under the other batch's FMA stream, so
// the fma pipe stays fed with only 2 warps/SMSP.
// ---------------------------------------------------------------------------
__global__ void __launch_bounds__(256,1) crf_forward(
    const float* __restrict__ em, const int* __restrict__ tags,
    const int* __restrict__ mask, const float* __restrict__ startt,
    const float* __restrict__ endt, const float* __restrict__ trans)
{
  __shared__ __align__(16) float pbuf[ENG][2][TT];   // [eng][batch][i], single-buffered
  __shared__ float kbuf[ENG][2][2];                  // [eng][batch][phase]
  __shared__ float red[ENG][8];

  const int tid  = threadIdx.x;
  const int eng  = tid >> 7;      // 0..1
  const int t    = tid & 127;     // owned state (column)
  const int lane = tid & 31;
  const int wrp  = t >> 5;
  const int barid = eng + 1;

  // ---- full E column in registers: 64 f32x2 pairs ----
  unsigned long long E2[64];
  #pragma unroll
  for (int q = 0; q < 64; ++q){
    float e0 = fex2(trans[(2*q  )*TT + t] * L2E);
    float e1 = fex2(trans[(2*q+1)*TT + t] * L2E);
    asm("mov.b64 %0,{%1,%2};":"=l"(E2[q]):"f"(e0),"f"(e1));
  }
  const float endj = endt[t];
  const float stj  = startt[t];

  const int ge  = eng*GRID_F + blockIdx.x;   // 0..295
  const int b0  = ge;
  const int b1v = ge + NENG;
  const bool has1 = (b1v < BB);
  const int b1  = has1 ? b1v : 0;

  const float* e0b = em + (long long)b0*SS*TT;
  const float* e1b = em + (long long)b1*SS*TT;
  const int*   mA  = mask + b0*SS;
  const int*   mB  = mask + b1*SS;

  // ---------------- numerator (gather path scores), trivial cost -----------
  float num0 = 0.f, num1 = 0.f;
  #pragma unroll
  for (int bt = 0; bt < 2; ++bt){
    const int b = bt ? b1 : b0;
    const int*   tg  = tags + b*SS;
    const int*   mb  = bt ? mB : mA;
    const float* ebb = bt ? e1b : e0b;
    float nacc = 0.f; int ncnt = 0;
    for (int s = t; s < SS; s += TT){
      int m = mb[s];
      ncnt += (m > 0);
      if (s > 0 && m > 0){
        int tp = tg[s-1], tc = tg[s];
        nacc += trans[tp*TT + tc] + ebb[s*TT + tc];
      }
    }
    #pragma unroll
    for (int o = 16; o; o >>= 1){
      nacc += __shfl_xor_sync(0xffffffffu, nacc, o);
      ncnt += __shfl_xor_sync(0xffffffffu, ncnt, o);
    }
    if (lane == 0){ red[eng][wrp] = nacc; ((int*)&red[eng][4])[wrp] = ncnt; }
    asm volatile("bar.sync %0,128;"::"r"(barid):"memory");
    if (t == 0){
      float na = red[eng][0] + red[eng][1] + red[eng][2] + red[eng][3];
      int   nc = ((int*)&red[eng][4])[0] + ((int*)&red[eng][4])[1]
               + ((int*)&red[eng][4])[2] + ((int*)&red[eng][4])[3];
      int t0 = tg[0];
      float nv = startt[t0] + ebb[t0] + na + endt[tg[nc-1]];
      if (bt) num1 = nv; else num0 = nv;
    }
    asm volatile("bar.sync %0,128;"::"r"(barid):"memory");
  }

  // ---------------- staggered dual forward recursion -----------------------
  float u0 = stj + e0b[t];
  float u1 = stj + e1b[t];
  float C0 = 0.f, C1 = 0.f;
  pbuf[eng][0][t] = fex2(u0 * L2E);     // p0(1)
  pbuf[eng][1][t] = fex2(u1 * L2E);     // p1(1)
  if (t == 0){ kbuf[eng][0][0] = u0; kbuf[eng][1][0] = u1; }

  // emission/mask pipelines:
  //  batch0: consumed at iter s -> em0[s];   prefetch em0[s+2]
  //  batch1: consumed at iter s -> em1[s-1]; prefetch em1[s+1]
  float emA0 = e0b[TT   + t], emB0 = e0b[2*TT + t];
  float emA1 = e1b[TT   + t], emB1 = e1b[2*TT + t];
  int   mkA0 = mA[1], mkB0 = mA[2];
  int   mkA1 = mB[1], mkB1 = mB[2];

  const ulonglong2* pA = (const ulonglong2*)&pbuf[eng][0][0];
  const ulonglong2* pB = (const ulonglong2*)&pbuf[eng][1][0];

  unsigned long long d0=0,d1=0,d2=0,d3=0;   // batch1 chains (in flight)

  for (int s = 1; s < SS; ++s){
    const int ph = s & 1;

    // ================= slot A: GEMV0(s) || tail1(s-1) =================
    asm volatile("bar.sync %0,128;"::"r"(barid):"memory");  // p0(s) ready

    unsigned long long c0=0,c1=0,c2=0,c3=0;
    #pragma unroll
    for (int q = 0; q < 32; ++q){
      ulonglong2 p = pA[q];
      if (q & 1){ FMA2(c2, E2[2*q], p.x, c2); FMA2(c3, E2[2*q+1], p.y, c3); }
      else      { FMA2(c0, E2[2*q], p.x, c0); FMA2(c1, E2[2*q+1], p.y, c1); }
    }

    if (s > 1){   // tail1(s-1): reduce d chains, update u1, publish p1(s)
      ADD2(d0,d0,d2); ADD2(d1,d1,d3); ADD2(d0,d0,d1);
      float lo, hi; UNPK(lo, hi, d0);
      float acc1 = lo + hi;
      float K1 = kbuf[eng][1][ph];          // phase of (s-1)-1 = s-2 -> (s)&1
      float v1 = fmaf(flg2(acc1), LN2, emA1);
      if (mkA1 > 0){ u1 = v1 - K1; C1 += K1; }
      if (t == 0) kbuf[eng][1][ph^1] = u1;  // phase (s-1)&1
      pbuf[eng][1][t] = fex2(u1 * L2E);     // p1(s)
      emA1 = emB1; mkA1 = mkB1;
      if (s + 1 < SS){ emB1 = e1b[(s+1)*TT + t]; mkB1 = mB[s+1]; }
    }

    // ================= slot B: GEMV1(s) || tail0(s) ===================
    asm volatile("bar.sync %0,128;"::"r"(barid):"memory");  // p1(s) ready

    d0=0; d1=0; d2=0; d3=0;
    #pragma unroll
    for (int q = 0; q < 32; ++q){
      ulonglong2 p = pB[q];
      if (q & 1){ FMA2(d2, E2[2*q], p.x, d2); FMA2(d3, E2[2*q+1], p.y, d3); }
      else      { FMA2(d0, E2[2*q], p.x, d0); FMA2(d1, E2[2*q+1], p.y, d1); }
    }

    {   // tail0(s): reduce c chains, update u0, publish p0(s+1)
      ADD2(c0,c0,c2); ADD2(c1,c1,c3); ADD2(c0,c0,c1);
      float lo, hi; UNPK(lo, hi, c0);
      float acc0 = lo + hi;
      float K0 = kbuf[eng][0][ph^1];        // phase (s-1)&1
      float v0 = fmaf(flg2(acc0), LN2, emA0);
      if (mkA0 > 0){ u0 = v0 - K0; C0 += K0; }
      if (t == 0) kbuf[eng][0][ph] = u0;    // phase s&1
      pbuf[eng][0][t] = fex2(u0 * L2E);     // p0(s+1)
      emA0 = emB0; mkA0 = mkB0;
      if (s + 2 < SS){ emB0 = e0b[(s+2)*TT + t]; mkB0 = mA[s+2]; }
    }
  }

  // epilogue: tail1(511) (chains d from last slot B; bar of last slot B
  // already ordered thread0's kbuf write vs this read)
  {
    ADD2(d0,d0,d2); ADD2(d1,d1,d3); ADD2(d0,d0,d1);
    float lo, hi; UNPK(lo, hi, d0);
    float acc1 = lo + hi;
    float K1 = kbuf[eng][1][(SS)&1];        // phase (511-1)&1 = 0 = SS&1
    float v1 = fmaf(flg2(acc1), LN2, emA1);
    if (mkA1 > 0){ u1 = v1 - K1; C1 += K1; }
  }

  // ---- final: denom_b = C + logsumexp_t(u_t + end_t) (exact max) ----------
  #pragma unroll
  for (int bt = 0; bt < 2; ++bt){
    float w = (bt ? u1 : u0) + endj;
    float m = w;
    #pragma unroll
    for (int o = 16; o; o >>= 1) m = fmaxf(m, __shfl_xor_sync(0xffffffffu, m, o));
    if (lane == 0) red[eng][wrp] = m;
    asm volatile("bar.sync %0,128;"::"r"(barid):"memory");
    m = fmaxf(fmaxf(red[eng][0], red[eng][1]), fmaxf(red[eng][2], red[eng][3]));
    float e = fex2((w - m) * L2E);
    #pragma unroll
    for (int o = 16; o; o >>= 1) e += __shfl_xor_sync(0xffffffffu, e, o);
    if (lane == 0) red[eng][4 + wrp] = e;
    asm volatile("bar.sync %0,128;"::"r"(barid):"memory");
    if (t == 0){
      float ssum = red[eng][4] + red[eng][5] + red[eng][6] + red[eng][7];
      float denomv = (bt ? C1 : C0) + m + flg2(ssum) * LN2;
      if (bt){ if (has1) g_res[b1] = num1 - denomv; }
      else   { g_res[b0] = num0 - denomv; }
    }
    asm volatile("bar.sync %0,128;"::"r"(barid):"memory");
  }
}

// ---------------------------------------------------------------------------
// Deterministic final reduction: out = sum_b g_res[b]
// ---------------------------------------------------------------------------
__global__ void crf_final(float* out)
{
  __shared__ float sm[256];
  int t = threadIdx.x;
  float a = 0.f;
  for (int b = t; b < BB; b += 256) a += g_res[b];
  sm[t] = a; __syncthreads();
  #pragma unroll
  for (int o = 128; o; o >>= 1){
    if (t < o) sm[t] += sm[t + o];
    __syncthreads();
  }
  if (t == 0) out[0] = sm[0];
}

extern "C" void kernel_launch(void* const* d_in, const int* in_sizes, int n_in,
                              void* d_out, int out_size)
{
  const float* em    = (const float*)d_in[0];
  const int*   tags  = (const int*)  d_in[1];
  const int*   mask  = (const int*)  d_in[2];
  const float* st    = (const float*)d_in[3];
  const float* en    = (const float*)d_in[4];
  const float* tr    = (const float*)d_in[5];
  float* out = (float*)d_out;

  crf_forward<<<GRID_F, 256>>>(em, tags, mask, st, en, tr);
  crf_final<<<1, 256>>>(out);
}